// round 4
// baseline (speedup 1.0000x reference)
#include <cuda_runtime.h>
#include <cuda_bf16.h>
#include <cstdint>

#define BB 2
#define NN 50
#define CC 80
#define MM 28
#define HH 800
#define WW 1333
#define HW (HH * WW)                          // 1,066,400 (divisible by 4)
#define MASK_ELEMS ((long long)BB * NN * HW)  // 106,640,000
#define CHUNK 2048                            // pixels per block (mult of 4)
#define NCHUNK ((HW + CHUNK - 1) / CHUNK)     // 521

// ---------------------------------------------------------------------------
// Single fused kernel, store-first ordering.
// Each block: one 2048-pixel flat chunk of one batch, all 50 output planes.
//  1. Build score-sorted instance table in shared (stable desc sort, N=50)
//     and y-cull to the chunk's row span (order-preserving compact).
//  2. Zero-blast the chunk across all 50 planes (fully unrolled STG.128
//     stream, fire-and-forget) -- no dependence on winners.
//  3. Compute winner bytes for this thread's 8 pixels while stores drain
//     (bit-exact reference float sequence; first hit in sorted order wins).
//  4. Overwrite winner pixels with 1.0f (same-thread program order => the
//     1.0 lands after the zero to the same address).
// ---------------------------------------------------------------------------
__global__ __launch_bounds__(256) void det2mask_fused(
    const float* __restrict__ mask_outs,
    const float* __restrict__ boxes,
    const float* __restrict__ scores,
    const int*   __restrict__ cls,
    float* __restrict__ out,
    int writeTail)
{
    const int b      = blockIdx.y;
    const int t      = threadIdx.x;
    const int base_p = blockIdx.x * CHUNK;

    __shared__ float4 s_box[NN];
    __shared__ float4 s_bnd[NN];
    __shared__ int2   s_inf[NN];
    __shared__ unsigned char s_list[NN];
    __shared__ unsigned s_ballot[2];

    // --- 1a. sorted table ------------------------------------------------
    if (t < NN) {
        int i = b * NN + t;
        float s = scores[i];
        int rank = 0;
        #pragma unroll 1
        for (int j = 0; j < NN; j++) {
            float sj = scores[b * NN + j];
            rank += (sj > s) || (sj == s && j < t);
        }
        float x0 = boxes[i * 4 + 0], y0 = boxes[i * 4 + 1];
        float x1 = boxes[i * 4 + 2], y1 = boxes[i * 4 + 3];
        s_box[rank] = make_float4(x0, y0, x1, y1);
        float bw = x1 - x0, bh = y1 - y0;
        s_bnd[rank] = make_float4(x0 - 0.05f * bw - 1.0f,
                                  x1 + 0.05f * bw + 1.0f,
                                  y0 - 0.05f * bh - 1.0f,
                                  y1 + 0.05f * bh + 1.0f);
        s_inf[rank] = make_int2((i * CC + cls[i]) * (MM * MM), t);
    }
    if (writeTail && blockIdx.x == 0 && b == 0 && t < BB * NN) {
        out[MASK_ELEMS + t] = scores[t];
        out[MASK_ELEMS + BB * NN + t] = (float)cls[t];
    }
    __syncthreads();

    // --- 1b. y-range cull ------------------------------------------------
    int pend = base_p + CHUNK; if (pend > HW) pend = HW;
    int y0r = base_p / WW;
    int y1r = (pend - 1) / WW;
    float tymin = (float)y0r + 0.5f, tymax = (float)y1r + 0.5f;

    if (t < 64) {
        bool hit = false;
        if (t < NN) {
            float4 bd = s_bnd[t];
            hit = (tymax >= bd.z) && (tymin <= bd.w);
        }
        unsigned m = __ballot_sync(0xffffffffu, hit);
        if ((t & 31) == 0) s_ballot[t >> 5] = m;
    }
    __syncthreads();
    if (t < 64) {
        unsigned m = s_ballot[t >> 5];
        if ((m >> (t & 31)) & 1u) {
            int pos = ((t >= 32) ? __popc(s_ballot[0]) : 0)
                      + __popc(m & ((1u << (t & 31)) - 1u));
            s_list[pos] = (unsigned char)t;
        }
    }
    __syncthreads();
    const int cnt = __popc(s_ballot[0]) + __popc(s_ballot[1]);

    // --- 2. zero-blast (independent of winners; issue first, fully
    //        unrolled so plane offsets fold into STG immediates) ----------
    {
        float* outb = out + b * (NN * HW) + base_p;
        const float4 z4 = make_float4(0.f, 0.f, 0.f, 0.f);
        const int g0 = t, g1 = 256 + t;
        const bool ok0 = (base_p + g0 * 4) < HW;
        const bool ok1 = (base_p + g1 * 4) < HW;
        float4* pl = reinterpret_cast<float4*>(outb);
        #pragma unroll
        for (int n = 0; n < NN; n++) {
            if (ok0) __stcs(pl + (n * (HW / 4) + g0), z4);
            if (ok1) __stcs(pl + (n * (HW / 4) + g1), z4);
        }
    }

    // --- 3. winner bytes for this thread's 8 pixels (overlaps store drain)
    unsigned wreg[2];
    #pragma unroll
    for (int k = 0; k < 2; k++) {
        unsigned wv = 0xffffffffu;
        int p0 = base_p + (k * 256 + t) * 4;
        if (p0 < HW && cnt > 0) {
            #pragma unroll
            for (int j = 0; j < 4; j++) {
                int p = p0 + j;
                int y = p / WW;
                int x = p - y * WW;
                float xc = (float)x + 0.5f;
                float yc = (float)y + 0.5f;
                int best = 255;
                #pragma unroll 1
                for (int kk = 0; kk < cnt; kk++) {
                    int si = s_list[kk];
                    float4 bd = s_bnd[si];
                    if (xc < bd.x || xc > bd.y || yc < bd.z || yc > bd.w) continue;
                    float4 bx = s_box[si];

                    float ty_  = __fdiv_rn(__fsub_rn(yc, bx.y), __fsub_rn(bx.w, bx.y));
                    float gy   = __fsub_rn(__fmul_rn(ty_, 2.0f), 1.0f);
                    float iy   = __fmul_rn(__fsub_rn(__fmul_rn(__fadd_rn(gy, 1.0f), 28.0f), 1.0f), 0.5f);
                    float iy0f = floorf(iy);
                    float wy   = __fsub_rn(iy, iy0f);

                    float tx_  = __fdiv_rn(__fsub_rn(xc, bx.x), __fsub_rn(bx.z, bx.x));
                    float gx   = __fsub_rn(__fmul_rn(tx_, 2.0f), 1.0f);
                    float ix   = __fmul_rn(__fsub_rn(__fmul_rn(__fadd_rn(gx, 1.0f), 28.0f), 1.0f), 0.5f);
                    float ix0f = floorf(ix);
                    float wx   = __fsub_rn(ix, ix0f);

                    int iy0 = (int)iy0f;
                    int ix0 = (int)ix0f;
                    if (iy0 < -1 || iy0 > MM - 1 || ix0 < -1 || ix0 > MM - 1) continue;

                    const float* mp = mask_outs + s_inf[si].x;
                    int r0 = iy0, r1 = iy0 + 1;
                    int c0 = ix0, c1 = ix0 + 1;
                    float v00 = (r0 >= 0 && c0 >= 0)           ? mp[r0 * MM + c0] : 0.0f;
                    float v01 = (r0 >= 0 && c1 <= MM - 1)      ? mp[r0 * MM + c1] : 0.0f;
                    float v10 = (r1 <= MM - 1 && c0 >= 0)      ? mp[r1 * MM + c0] : 0.0f;
                    float v11 = (r1 <= MM - 1 && c1 <= MM - 1) ? mp[r1 * MM + c1] : 0.0f;

                    float omwy = __fsub_rn(1.0f, wy);
                    float rr0  = __fadd_rn(__fmul_rn(v00, omwy), __fmul_rn(v10, wy));
                    float rr1  = __fadd_rn(__fmul_rn(v01, omwy), __fmul_rn(v11, wy));
                    float omwx = __fsub_rn(1.0f, wx);
                    float soft = __fadd_rn(__fmul_rn(rr0, omwx), __fmul_rn(rr1, wx));

                    if (soft >= 0.5f) { best = s_inf[si].y; break; }
                }
                wv = (wv & ~(0xffu << (j * 8))) | ((unsigned)best << (j * 8));
            }
        }
        wreg[k] = wv;
    }

    // --- 4. overwrite winner pixels with 1.0 (same thread => ordered) ----
    #pragma unroll
    for (int k = 0; k < 2; k++) {
        unsigned wv = wreg[k];
        if (wv == 0xffffffffu) continue;
        int p0 = base_p + (k * 256 + t) * 4;
        #pragma unroll
        for (int j = 0; j < 4; j++) {
            unsigned n = (wv >> (j * 8)) & 0xffu;
            if (n != 0xffu) {
                out[b * (NN * HW) + (int)n * HW + p0 + j] = 1.0f;
            }
        }
    }
}

extern "C" void kernel_launch(void* const* d_in, const int* in_sizes, int n_in,
                              void* d_out, int out_size)
{
    const float* mask_outs = (const float*)d_in[0];
    const float* boxes     = (const float*)d_in[1];
    const float* scores    = (const float*)d_in[2];
    const int*   cls       = (const int*)d_in[3];
    float* out = (float*)d_out;

    int writeTail = ((long long)out_size >= MASK_ELEMS + 2 * BB * NN) ? 1 : 0;
    dim3 grid(NCHUNK, BB);
    det2mask_fused<<<grid, 256>>>(mask_outs, boxes, scores, cls, out, writeTail);
}

// round 5
// speedup vs baseline: 1.0417x; 1.0417x over previous
#include <cuda_runtime.h>
#include <cuda_bf16.h>
#include <cstdint>

#define BB 2
#define NN 50
#define CC 80
#define MM 28
#define HH 800
#define WW 1333
#define HW (HH * WW)                          // 1,066,400
#define MASK_ELEMS ((long long)BB * NN * HW)  // 106,640,000
#define CHUNK 2048                            // pixels per block
#define NCHUNK ((HW + CHUNK - 1) / CHUNK)     // 521 (last chunk = 1440 px)

__device__ __forceinline__ uint32_t smem_u32(const void* p) {
    uint32_t a;
    asm("{ .reg .u64 t; cvta.to.shared.u64 t, %1; cvt.u32.u64 %0, t; }"
        : "=r"(a) : "l"(p));
    return a;
}
__device__ __forceinline__ void bulk_store_1d(void* gdst, uint32_t ssrc, uint32_t bytes) {
    asm volatile("cp.async.bulk.global.shared::cta.bulk_group [%0], [%1], %2;"
                 :: "l"(gdst), "r"(ssrc), "r"(bytes) : "memory");
}

// ---------------------------------------------------------------------------
// Single fused kernel; zeros go out via async-proxy bulk stores so winner
// compute overlaps the drain without L1tex-queue contention.
//  1. sorted instance table + y-cull (order-preserving => first soft>=0.5
//     hit in sorted order IS the reference winner).
//  2. zero 8KB SMEM staging; elected thread issues 50 1D bulk stores.
//  3. winner bytes per thread (bit-exact reference float sequence) -- runs
//     while bulk stores drain.
//  4. wait_group 0 + fence.proxy.async + syncthreads, then sparse 1.0
//     overwrites (ordered after the zeros).
// ---------------------------------------------------------------------------
__global__ __launch_bounds__(256) void det2mask_fused(
    const float* __restrict__ mask_outs,
    const float* __restrict__ boxes,
    const float* __restrict__ scores,
    const int*   __restrict__ cls,
    float* __restrict__ out,
    int writeTail)
{
    const int b      = blockIdx.y;
    const int t      = threadIdx.x;
    const int base_p = blockIdx.x * CHUNK;

    __shared__ __align__(16) float s_zero[CHUNK];   // 8 KB staging (all zeros)
    __shared__ float4 s_box[NN];
    __shared__ float4 s_bnd[NN];
    __shared__ int2   s_inf[NN];
    __shared__ unsigned char s_list[NN];
    __shared__ unsigned s_ballot[2];

    // --- 1a. sorted table + zero staging ---------------------------------
    {
        float4* z = reinterpret_cast<float4*>(s_zero);
        const float4 z4 = make_float4(0.f, 0.f, 0.f, 0.f);
        z[t] = z4;
        z[t + 256] = z4;
    }
    if (t < NN) {
        int i = b * NN + t;
        float s = scores[i];
        int rank = 0;
        #pragma unroll 1
        for (int j = 0; j < NN; j++) {
            float sj = scores[b * NN + j];
            rank += (sj > s) || (sj == s && j < t);
        }
        float x0 = boxes[i * 4 + 0], y0 = boxes[i * 4 + 1];
        float x1 = boxes[i * 4 + 2], y1 = boxes[i * 4 + 3];
        s_box[rank] = make_float4(x0, y0, x1, y1);
        float bw = x1 - x0, bh = y1 - y0;
        s_bnd[rank] = make_float4(x0 - 0.05f * bw - 1.0f,
                                  x1 + 0.05f * bw + 1.0f,
                                  y0 - 0.05f * bh - 1.0f,
                                  y1 + 0.05f * bh + 1.0f);
        s_inf[rank] = make_int2((i * CC + cls[i]) * (MM * MM), t);
    }
    if (writeTail && blockIdx.x == 0 && b == 0 && t < BB * NN) {
        out[MASK_ELEMS + t] = scores[t];
        out[MASK_ELEMS + BB * NN + t] = (float)cls[t];
    }
    __syncthreads();

    // --- 1b. y-range cull -------------------------------------------------
    int pend = base_p + CHUNK; if (pend > HW) pend = HW;
    const int npix = pend - base_p;                 // 2048 or 1440
    int y0r = base_p / WW;
    int y1r = (pend - 1) / WW;
    float tymin = (float)y0r + 0.5f, tymax = (float)y1r + 0.5f;

    if (t < 64) {
        bool hit = false;
        if (t < NN) {
            float4 bd = s_bnd[t];
            hit = (tymax >= bd.z) && (tymin <= bd.w);
        }
        unsigned m = __ballot_sync(0xffffffffu, hit);
        if ((t & 31) == 0) s_ballot[t >> 5] = m;
    }
    __syncthreads();
    if (t < 64) {
        unsigned m = s_ballot[t >> 5];
        if ((m >> (t & 31)) & 1u) {
            int pos = ((t >= 32) ? __popc(s_ballot[0]) : 0)
                      + __popc(m & ((1u << (t & 31)) - 1u));
            s_list[pos] = (unsigned char)t;
        }
    }
    __syncthreads();
    const int cnt = __popc(s_ballot[0]) + __popc(s_ballot[1]);

    // --- 2. async-proxy zero stores (elected thread, fire-and-forget) -----
    if (t == 0) {
        asm volatile("fence.proxy.async.shared::cta;" ::: "memory");
        uint32_t src = smem_u32(s_zero);
        float* outb = out + b * (NN * HW) + base_p;
        uint32_t bytes = (uint32_t)npix * 4u;
        #pragma unroll 1
        for (int n = 0; n < NN; n++) {
            bulk_store_1d(outb + n * HW, src, bytes);
        }
        asm volatile("cp.async.bulk.commit_group;" ::: "memory");
    }

    // --- 3. winner bytes (overlaps bulk-store drain) ----------------------
    unsigned wreg[2];
    #pragma unroll
    for (int k = 0; k < 2; k++) {
        unsigned wv = 0xffffffffu;
        int p0 = base_p + (k * 256 + t) * 4;
        if (p0 < HW && cnt > 0) {
            #pragma unroll
            for (int j = 0; j < 4; j++) {
                int p = p0 + j;
                int y = p / WW;
                int x = p - y * WW;
                float xc = (float)x + 0.5f;
                float yc = (float)y + 0.5f;
                int best = 255;
                #pragma unroll 1
                for (int kk = 0; kk < cnt; kk++) {
                    int si = s_list[kk];
                    float4 bd = s_bnd[si];
                    if (xc < bd.x || xc > bd.y || yc < bd.z || yc > bd.w) continue;
                    float4 bx = s_box[si];

                    float ty_  = __fdiv_rn(__fsub_rn(yc, bx.y), __fsub_rn(bx.w, bx.y));
                    float gy   = __fsub_rn(__fmul_rn(ty_, 2.0f), 1.0f);
                    float iy   = __fmul_rn(__fsub_rn(__fmul_rn(__fadd_rn(gy, 1.0f), 28.0f), 1.0f), 0.5f);
                    float iy0f = floorf(iy);
                    float wy   = __fsub_rn(iy, iy0f);

                    float tx_  = __fdiv_rn(__fsub_rn(xc, bx.x), __fsub_rn(bx.z, bx.x));
                    float gx   = __fsub_rn(__fmul_rn(tx_, 2.0f), 1.0f);
                    float ix   = __fmul_rn(__fsub_rn(__fmul_rn(__fadd_rn(gx, 1.0f), 28.0f), 1.0f), 0.5f);
                    float ix0f = floorf(ix);
                    float wx   = __fsub_rn(ix, ix0f);

                    int iy0 = (int)iy0f;
                    int ix0 = (int)ix0f;
                    if (iy0 < -1 || iy0 > MM - 1 || ix0 < -1 || ix0 > MM - 1) continue;

                    const float* mp = mask_outs + s_inf[si].x;
                    int r0 = iy0, r1 = iy0 + 1;
                    int c0 = ix0, c1 = ix0 + 1;
                    float v00 = (r0 >= 0 && c0 >= 0)           ? mp[r0 * MM + c0] : 0.0f;
                    float v01 = (r0 >= 0 && c1 <= MM - 1)      ? mp[r0 * MM + c1] : 0.0f;
                    float v10 = (r1 <= MM - 1 && c0 >= 0)      ? mp[r1 * MM + c0] : 0.0f;
                    float v11 = (r1 <= MM - 1 && c1 <= MM - 1) ? mp[r1 * MM + c1] : 0.0f;

                    float omwy = __fsub_rn(1.0f, wy);
                    float rr0  = __fadd_rn(__fmul_rn(v00, omwy), __fmul_rn(v10, wy));
                    float rr1  = __fadd_rn(__fmul_rn(v01, omwy), __fmul_rn(v11, wy));
                    float omwx = __fsub_rn(1.0f, wx);
                    float soft = __fadd_rn(__fmul_rn(rr0, omwx), __fmul_rn(rr1, wx));

                    if (soft >= 0.5f) { best = s_inf[si].y; break; }
                }
                wv = (wv & ~(0xffu << (j * 8))) | ((unsigned)best << (j * 8));
            }
        }
        wreg[k] = wv;
    }

    // --- 4. order zeros before the sparse 1.0 overwrites ------------------
    if (t == 0) {
        asm volatile("cp.async.bulk.wait_group 0;" ::: "memory");
        asm volatile("fence.proxy.async;" ::: "memory");
    }
    __syncthreads();

    #pragma unroll
    for (int k = 0; k < 2; k++) {
        unsigned wv = wreg[k];
        if (wv == 0xffffffffu) continue;
        int p0 = base_p + (k * 256 + t) * 4;
        #pragma unroll
        for (int j = 0; j < 4; j++) {
            unsigned n = (wv >> (j * 8)) & 0xffu;
            if (n != 0xffu) {
                out[b * (NN * HW) + (int)n * HW + p0 + j] = 1.0f;
            }
        }
    }
}

extern "C" void kernel_launch(void* const* d_in, const int* in_sizes, int n_in,
                              void* d_out, int out_size)
{
    const float* mask_outs = (const float*)d_in[0];
    const float* boxes     = (const float*)d_in[1];
    const float* scores    = (const float*)d_in[2];
    const int*   cls       = (const int*)d_in[3];
    float* out = (float*)d_out;

    int writeTail = ((long long)out_size >= MASK_ELEMS + 2 * BB * NN) ? 1 : 0;
    dim3 grid(NCHUNK, BB);
    det2mask_fused<<<grid, 256>>>(mask_outs, boxes, scores, cls, out, writeTail);
}